// round 9
// baseline (speedup 1.0000x reference)
#include <cuda_runtime.h>
#include <cstdint>

#define NPG 524288           // elements per (b, group)
#define NTOT 33554432        // B*C*H*W

// ---------------- device scratch (static allocation only) ----------------
static __device__ float  d_part[1024 * 2];    // per-block GN partials (sum, sumsq)
static __device__ float  d_weff[8 * 8192];    // [b][k][c*2 + {0=gate,1=upd}]
static __device__ float  d_biaseff[8 * 128];
static __device__ float  d_gate[NTOT];        // sigmoid(gate logits)
static __device__ float  d_hw[NTOT];          // column-scan result

// ---------------- f32x2 packed FMA helpers --------------------------------
__device__ __forceinline__ unsigned long long fma2(unsigned long long a,
                                                   unsigned long long b,
                                                   unsigned long long c) {
    unsigned long long d;
    asm("fma.rn.f32x2 %0, %1, %2, %3;" : "=l"(d) : "l"(a), "l"(b), "l"(c));
    return d;
}
__device__ __forceinline__ unsigned long long pack2(float lo, float hi) {
    unsigned long long d;
    asm("mov.b64 %0, {%1, %2};" : "=l"(d) : "f"(lo), "f"(hi));
    return d;
}
__device__ __forceinline__ void unpack2(unsigned long long v, float& lo, float& hi) {
    asm("mov.b64 {%0, %1}, %2;" : "=f"(lo), "=f"(hi) : "l"(v));
}
// sigmoid(z) = 0.5*tanh(0.5z) + 0.5 via MUFU.TANH (1 MUFU + 2 FMA)
__device__ __forceinline__ float sigmoid_tanh(float z) {
    float t;
    asm("tanh.approx.f32 %0, %1;" : "=f"(t) : "f"(z * 0.5f));
    return fmaf(0.5f, t, 0.5f);
}

// ---------------- K1: GN partial stats (atomic-free) ---------------------
__global__ __launch_bounds__(256) void k_gn_stats(const float* __restrict__ x) {
    const int grp   = blockIdx.x >> 4;
    const int slice = blockIdx.x & 15;
    const float4* p = (const float4*)x + (size_t)grp * 131072 + slice * 8192;
    float s = 0.f, ss = 0.f;
#pragma unroll 4
    for (int i = threadIdx.x; i < 8192; i += 256) {
        float4 v = p[i];
        s  += (v.x + v.y) + (v.z + v.w);
        ss += (v.x * v.x + v.y * v.y) + (v.z * v.z + v.w * v.w);
    }
    for (int off = 16; off; off >>= 1) {
        s  += __shfl_down_sync(0xffffffffu, s,  off);
        ss += __shfl_down_sync(0xffffffffu, ss, off);
    }
    __shared__ float rs[8], rss[8];
    int w = threadIdx.x >> 5, l = threadIdx.x & 31;
    if (l == 0) { rs[w] = s; rss[w] = ss; }
    __syncthreads();
    if (threadIdx.x == 0) {
        float S = 0.f, SS = 0.f;
#pragma unroll
        for (int i = 0; i < 8; i++) { S += rs[i]; SS += rss[i]; }
        d_part[blockIdx.x * 2 + 0] = S;
        d_part[blockIdx.x * 2 + 1] = SS;
    }
}

// ---------------- K2: finalize stats + fold GN affine into weights -------
__global__ __launch_bounds__(256) void k_weff(const float* __restrict__ gw,
                                              const float* __restrict__ gb,
                                              const float* __restrict__ uw,
                                              const float* __restrict__ ub,
                                              const float* __restrict__ gnw,
                                              const float* __restrict__ gnb) {
    const int b = blockIdx.x >> 3;
    const int slice = blockIdx.x & 7;
    __shared__ float smu[8], srstd[8];
    if (threadIdx.x < 8) {
        int g = b * 8 + threadIdx.x;
        double S = 0.0, SS = 0.0;
#pragma unroll
        for (int i = 0; i < 16; i++) {
            S  += (double)d_part[(g * 16 + i) * 2 + 0];
            SS += (double)d_part[(g * 16 + i) * 2 + 1];
        }
        const double n = (double)NPG;
        double mu  = S / n;
        double var = SS / n - mu * mu;
        smu[threadIdx.x]   = (float)mu;
        srstd[threadIdx.x] = (float)(1.0 / sqrt(var + 1e-5));
    }
    __syncthreads();
    const int base = slice * 1024;
#pragma unroll 4
    for (int i = 0; i < 4; i++) {
        int idx = base + i * 256 + threadIdx.x;
        int k = idx >> 7, o = idx & 127;
        float w = (o < 64) ? gw[o * 64 + k] : uw[(o - 64) * 64 + k];
        // interleaved: [k][c*2 + {0=gate,1=upd}]
        d_weff[b * 8192 + k * 128 + (o & 63) * 2 + (o >> 6)] =
            w * gnw[k] * srstd[k >> 3];
    }
    if (slice == 0 && threadIdx.x < 128) {
        int o = threadIdx.x;
        float acc = (o < 64) ? gb[o] : ub[o - 64];
#pragma unroll 8
        for (int k = 0; k < 64; k++) {
            float w = (o < 64) ? gw[o * 64 + k] : uw[(o - 64) * 64 + k];
            int g = k >> 3;
            acc += w * (gnb[k] - smu[g] * srstd[g] * gnw[k]);
        }
        d_biaseff[b * 128 + o] = acc;
    }
}

// ---------------- K3: fused 1x1 convs + column scan over W ---------------
// Grid 2048 = 8 b x 256 h. 128 threads: c = t>>1, wg = t&1 (16-px group).
// Per k per thread: 1 LDS.64 + 4 broadcast LDS.128 -> 16 FFMA2. 4 CTAs/SM.
// hv is DOUBLE-BUFFERED: 1 barrier per chunk; STS of chunk c+1 overlaps
// the matvec of chunk c; LDG prefetch runs 2 chunks ahead.
__global__ __launch_bounds__(128, 4) void k_colscan(const float* __restrict__ x) {
    __shared__ float wsm[64 * 128];   // 32KB: [k][c*2 + {g,u}]
    __shared__ float hv[2][64 * 36];  // 18.4KB: [buf][k][32 px + 4 pad]

    const int t  = threadIdx.x;
    const int b  = blockIdx.x >> 8;
    const int h  = blockIdx.x & 255;
    const int c  = t >> 1;
    const int wg = t & 1;

    {
        const float4* wsrc = (const float4*)(d_weff + b * 8192);
        float4* wdst = (float4*)wsm;
#pragma unroll
        for (int i = 0; i < 16; i++) wdst[t + i * 128] = wsrc[t + i * 128];
    }
    const float bg = d_biaseff[b * 128 + c];
    const float bu = d_biaseff[b * 128 + 64 + c];

    // loader slots: sl = t + i*128 -> channel sl>>3, float4 slot sl&7
    const float* xb = x + (size_t)b * 64 * 65536 + h * 256;
    int soff[4];
    const float* gptr[4];
#pragma unroll
    for (int i = 0; i < 4; i++) {
        int sl = t + i * 128;
        gptr[i] = xb + (size_t)(sl >> 3) * 65536 + (sl & 7) * 4;
        soff[i] = (sl >> 3) * 36 + (sl & 7) * 4;
    }

    // prologue: chunk0 -> hv[0]; vin <- chunk1
    float4 vin[4];
#pragma unroll
    for (int i = 0; i < 4; i++) *(float4*)&hv[0][soff[i]] = *(const float4*)gptr[i];
#pragma unroll
    for (int i = 0; i < 4; i++) vin[i] = *(const float4*)(gptr[i] + 32);
    __syncthreads();                   // hv[0] + wsm visible

    float s_prev = 0.f;
    const unsigned FULL = 0xffffffffu;

#pragma unroll 1
    for (int chk = 0; chk < 8; chk++) {
        const int buf = chk & 1;
        // stage chunk chk+1 into the other buffer (its readers synced last iter)
        if (chk < 7) {
#pragma unroll
            for (int i = 0; i < 4; i++) *(float4*)&hv[buf ^ 1][soff[i]] = vin[i];
        }
        // prefetch chunk chk+2
        if (chk < 6) {
#pragma unroll
            for (int i = 0; i < 4; i++)
                vin[i] = *(const float4*)(gptr[i] + (chk + 2) * 32);
        }

        // ---- matvec: 16 pixels x {gate, upd} from hv[buf] ----
        unsigned long long ag[8], au[8];
        const unsigned long long bg2 = pack2(bg, bg);
        const unsigned long long bu2 = pack2(bu, bu);
#pragma unroll
        for (int j = 0; j < 8; j++) { ag[j] = bg2; au[j] = bu2; }
        const float* hb = hv[buf] + wg * 16;
#pragma unroll
        for (int k = 0; k < 64; k++) {
            float2 wv = *(const float2*)&wsm[k * 128 + c * 2];
            unsigned long long w2g = pack2(wv.x, wv.x);
            unsigned long long w2u = pack2(wv.y, wv.y);
#pragma unroll
            for (int j = 0; j < 4; j++) {
                ulonglong2 hp = *(const ulonglong2*)(hb + k * 36 + j * 4);
                ag[2*j]   = fma2(w2g, hp.x, ag[2*j]);
                au[2*j]   = fma2(w2u, hp.x, au[2*j]);
                ag[2*j+1] = fma2(w2g, hp.y, ag[2*j+1]);
                au[2*j+1] = fma2(w2u, hp.y, au[2*j+1]);
            }
        }
        float gv[16], uv[16];
#pragma unroll
        for (int j = 0; j < 8; j++) {
            unpack2(ag[j], gv[2*j], gv[2*j+1]);
            unpack2(au[j], uv[2*j], uv[2*j+1]);
        }
        // gv -> sigmoid(gate); uv -> (1-g)*u
#pragma unroll
        for (int j = 0; j < 16; j++) {
            gv[j] = sigmoid_tanh(gv[j]);
            uv[j] = fmaf(-gv[j], uv[j], uv[j]);
        }

        // ---- composite over own 16 px ----
        float Ac = 1.f, Bc = 0.f;
#pragma unroll
        for (int j = 0; j < 16; j++) {
            Ac = Ac * gv[j];
            Bc = fmaf(gv[j], Bc, uv[j]);
        }
        // exchange with neighbour 16-px group (lane^1)
        float Ao = __shfl_xor_sync(FULL, Ac, 1);
        float Bo = __shfl_xor_sync(FULL, Bc, 1);
        float Af = (wg == 0) ? Ac : Ao;   // first-half composite
        float Bf = (wg == 0) ? Bc : Bo;
        float As = (wg == 0) ? Ao : Ac;   // second-half composite
        float Bs = (wg == 0) ? Bo : Bc;
        float sin = (wg == 0) ? s_prev : fmaf(Af, s_prev, Bf);
        s_prev = fmaf(As, fmaf(Af, s_prev, Bf), Bs);

        // ---- sequential re-apply + writeback (4+4 STG.128) ----
        int gi = (((b * 64 + c) * 256 + h) * 256) + chk * 32 + wg * 16;
        float s = sin;
#pragma unroll
        for (int q = 0; q < 4; q++) {
            float4 sv4;
            s = fmaf(gv[4*q+0], s, uv[4*q+0]); sv4.x = s;
            s = fmaf(gv[4*q+1], s, uv[4*q+1]); sv4.y = s;
            s = fmaf(gv[4*q+2], s, uv[4*q+2]); sv4.z = s;
            s = fmaf(gv[4*q+3], s, uv[4*q+3]); sv4.w = s;
            *(float4*)(d_gate + gi + q * 4) =
                make_float4(gv[4*q], gv[4*q+1], gv[4*q+2], gv[4*q+3]);
            *(float4*)(d_hw + gi + q * 4) = sv4;
        }
        __syncthreads();   // next-chunk staging visible; this buf free next iter
    }
}

// ---------------- K4: row scan over H + residual add ---------------------
// Scalar, 131072 threads (1024 x 128). Loads for 8 h-steps explicitly
// batched (24 independent LDG.32 in flight) before the serial scan math.
__global__ __launch_bounds__(128) void k_rowscan(const float* __restrict__ x,
                                                 float* __restrict__ out) {
    const int idx  = blockIdx.x * 128 + threadIdx.x;     // 0..131071
    const int base = (idx >> 8) * 65536 + (idx & 255);   // (b*64+c)*HW + w
    float s = 0.f;
#pragma unroll 1
    for (int h = 0; h < 256; h += 8) {
        const int r = base + (h << 8);
        float g[8], u[8], xv[8];
#pragma unroll
        for (int j = 0; j < 8; j++) g[j] = d_gate[r + (j << 8)];
#pragma unroll
        for (int j = 0; j < 8; j++) u[j] = d_hw[r + (j << 8)];
#pragma unroll
        for (int j = 0; j < 8; j++) xv[j] = __ldcs(&x[r + (j << 8)]);
#pragma unroll
        for (int j = 0; j < 8; j++) {
            s = fmaf(g[j], s, fmaf(-g[j], u[j], u[j]));
            __stcs(&out[r + (j << 8)], xv[j] + s);
        }
    }
}

// ---------------- launch --------------------------------------------------
extern "C" void kernel_launch(void* const* d_in, const int* in_sizes, int n_in,
                              void* d_out, int out_size) {
    const float* x      = (const float*)d_in[0];
    const float* gn_w   = (const float*)d_in[1];
    const float* gn_b   = (const float*)d_in[2];
    const float* gate_w = (const float*)d_in[3];
    const float* gate_b = (const float*)d_in[4];
    const float* upd_w  = (const float*)d_in[5];
    const float* upd_b  = (const float*)d_in[6];
    float* out = (float*)d_out;

    k_gn_stats<<<1024, 256>>>(x);
    k_weff<<<64, 256>>>(gate_w, gate_b, upd_w, upd_b, gn_w, gn_b);
    k_colscan<<<2048, 128>>>(x);
    k_rowscan<<<1024, 128>>>(x, out);
}